// round 3
// baseline (speedup 1.0000x reference)
#include <cuda_runtime.h>
#include <cstddef>

#define NB     4
#define CIN    256
#define CDIM   512
#define HIN    56
#define NNF    3136      // 56*56
#define PQ     784       // 28*28
#define NHEADS 8
#define HD     64
#define SCALE  0.125f

// ---------------- scratch layout (single __device__ array) ----------------
#define SZ_MAP  1605632ull     // 4*512*784
#define SZ_TQ   802816ull      // 4*256*784
#define SZ_KV   6422528ull     // 4*512*3136
#define SZ_ATT  78675968ull    // 4*8*784*3136

#define OFF_XPROJ 0ull
#define OFF_TQ    (OFF_XPROJ + SZ_MAP)
#define OFF_Q     (OFF_TQ    + SZ_TQ)
#define OFF_QN    (OFF_Q     + SZ_MAP)
#define OFF_K     (OFF_QN    + SZ_MAP)
#define OFF_V     (OFF_K     + SZ_KV)
#define OFF_VLOC  (OFF_V     + SZ_KV)
#define OFF_O1    (OFF_VLOC  + SZ_MAP)
#define OFF_O2    (OFF_O1    + SZ_MAP)
#define OFF_S1    (OFF_O2    + SZ_MAP)
#define OFF_A2    (OFF_S1    + SZ_ATT)
#define SCRATCH_TOTAL (OFF_A2 + SZ_ATT)   // 180,633,600 floats (~722 MB)

__device__ float g_scratch[SCRATCH_TOTAL];

// ---------------- generic tiled GEMM for 1x1 convs ----------------
// Y[b][m][p] = sum_k A[m][k] * X[b][k][p]  (+bias[m]), optional hardswish on X
__global__ __launch_bounds__(256)
void gemm1x1_kernel(const float* __restrict__ A, const float* __restrict__ X,
                    const float* __restrict__ bias, float* __restrict__ Y,
                    int M, int K, int P, int hsw)
{
    __shared__ __align__(16) float As[64 * 17];
    __shared__ __align__(16) float Xs[16 * 68];
    int b  = blockIdx.z;
    int m0 = blockIdx.y * 64;
    int p0 = blockIdx.x * 64;
    int t  = threadIdx.x;
    int ty = t >> 4, tx = t & 15;

    float acc[4][4];
#pragma unroll
    for (int i = 0; i < 4; i++)
#pragma unroll
        for (int j = 0; j < 4; j++) acc[i][j] = 0.f;

    for (int k0 = 0; k0 < K; k0 += 16) {
#pragma unroll
        for (int it = 0; it < 4; it++) {
            int idx = t + it * 256;
            int m = idx >> 4, k = idx & 15;
            As[m * 17 + k] = A[(size_t)(m0 + m) * K + k0 + k];
        }
#pragma unroll
        for (int it = 0; it < 4; it++) {
            int idx = t + it * 256;
            int kk = idx >> 6, pp = idx & 63;
            int p = p0 + pp;
            float v = 0.f;
            if (p < P) v = X[((size_t)b * K + k0 + kk) * P + p];
            if (hsw) {
                float c = fminf(fmaxf(v + 3.f, 0.f), 6.f);
                v = v * c * (1.f / 6.f);
            }
            Xs[kk * 68 + pp] = v;
        }
        __syncthreads();
#pragma unroll
        for (int kk = 0; kk < 16; kk++) {
            float a0 = As[(ty * 4 + 0) * 17 + kk];
            float a1 = As[(ty * 4 + 1) * 17 + kk];
            float a2 = As[(ty * 4 + 2) * 17 + kk];
            float a3 = As[(ty * 4 + 3) * 17 + kk];
            float4 xv = *(const float4*)&Xs[kk * 68 + tx * 4];
            acc[0][0] += a0 * xv.x; acc[0][1] += a0 * xv.y; acc[0][2] += a0 * xv.z; acc[0][3] += a0 * xv.w;
            acc[1][0] += a1 * xv.x; acc[1][1] += a1 * xv.y; acc[1][2] += a1 * xv.z; acc[1][3] += a1 * xv.w;
            acc[2][0] += a2 * xv.x; acc[2][1] += a2 * xv.y; acc[2][2] += a2 * xv.z; acc[2][3] += a2 * xv.w;
            acc[3][0] += a3 * xv.x; acc[3][1] += a3 * xv.y; acc[3][2] += a3 * xv.z; acc[3][3] += a3 * xv.w;
        }
        __syncthreads();
    }
#pragma unroll
    for (int i = 0; i < 4; i++) {
        int m = m0 + ty * 4 + i;
        float bv = bias ? bias[m] : 0.f;
        float* yb = Y + ((size_t)b * M + m) * P;
#pragma unroll
        for (int j = 0; j < 4; j++) {
            int p = p0 + tx * 4 + j;
            if (p < P) yb[p] = acc[i][j] + bv;
        }
    }
}

// ---------------- implicit-GEMM 3x3 stride-2 pad-1 conv (grouped) ----------------
// in: 56x56, out: 28x28.  co tile = 64; group g = (co_tile)/CoutPG.
__global__ __launch_bounds__(256)
void conv3x3_kernel(const float* __restrict__ X, const float* __restrict__ W,
                    const float* __restrict__ bias, float* __restrict__ Y,
                    int CinPG, int CinTot, int CoutPG, int Cout)
{
    __shared__ __align__(16) float As[64 * 17];
    __shared__ __align__(16) float Xs[16 * 68];
    int b  = blockIdx.z;
    int m0 = blockIdx.y * 64;
    int p0 = blockIdx.x * 64;
    int g  = m0 / CoutPG;
    int K  = CinPG * 9;
    int t  = threadIdx.x;
    int ty = t >> 4, tx = t & 15;

    const float* Xb = X + (size_t)(b * CinTot + g * CinPG) * NNF;

    float acc[4][4];
#pragma unroll
    for (int i = 0; i < 4; i++)
#pragma unroll
        for (int j = 0; j < 4; j++) acc[i][j] = 0.f;

    for (int k0 = 0; k0 < K; k0 += 16) {
#pragma unroll
        for (int it = 0; it < 4; it++) {
            int idx = t + it * 256;
            int m = idx >> 4, k = idx & 15;
            As[m * 17 + k] = W[(size_t)(m0 + m) * K + k0 + k];
        }
#pragma unroll
        for (int it = 0; it < 4; it++) {
            int idx = t + it * 256;
            int kk = idx >> 6, pp = idx & 63;
            int k = k0 + kk;
            int ci = k / 9, r9 = k - ci * 9;
            int ky = r9 / 3, kx = r9 - ky * 3;
            int p = p0 + pp;
            float v = 0.f;
            if (p < PQ) {
                int py = p / 28, px = p - py * 28;
                int iy = 2 * py - 1 + ky, ix = 2 * px - 1 + kx;
                if ((unsigned)iy < (unsigned)HIN && (unsigned)ix < (unsigned)HIN)
                    v = Xb[(size_t)ci * NNF + iy * HIN + ix];
            }
            Xs[kk * 68 + pp] = v;
        }
        __syncthreads();
#pragma unroll
        for (int kk = 0; kk < 16; kk++) {
            float a0 = As[(ty * 4 + 0) * 17 + kk];
            float a1 = As[(ty * 4 + 1) * 17 + kk];
            float a2 = As[(ty * 4 + 2) * 17 + kk];
            float a3 = As[(ty * 4 + 3) * 17 + kk];
            float4 xv = *(const float4*)&Xs[kk * 68 + tx * 4];
            acc[0][0] += a0 * xv.x; acc[0][1] += a0 * xv.y; acc[0][2] += a0 * xv.z; acc[0][3] += a0 * xv.w;
            acc[1][0] += a1 * xv.x; acc[1][1] += a1 * xv.y; acc[1][2] += a1 * xv.z; acc[1][3] += a1 * xv.w;
            acc[2][0] += a2 * xv.x; acc[2][1] += a2 * xv.y; acc[2][2] += a2 * xv.z; acc[2][3] += a2 * xv.w;
            acc[3][0] += a3 * xv.x; acc[3][1] += a3 * xv.y; acc[3][2] += a3 * xv.z; acc[3][3] += a3 * xv.w;
        }
        __syncthreads();
    }
#pragma unroll
    for (int i = 0; i < 4; i++) {
        int m = m0 + ty * 4 + i;
        float bv = bias ? bias[m] : 0.f;
        float* yb = Y + ((size_t)b * Cout + m) * PQ;
#pragma unroll
        for (int j = 0; j < 4; j++) {
            int p = p0 + tx * 4 + j;
            if (p < PQ) yb[p] = acc[i][j] + bv;
        }
    }
}

// ---------------- GroupNorm (in-place or to dst, optional residual add) ----------------
__global__ __launch_bounds__(256)
void gn_kernel(float* __restrict__ data, const float* __restrict__ w,
               const float* __restrict__ bgn, int HW,
               const float* __restrict__ addsrc, float* __restrict__ dst)
{
    __shared__ float rs[256], rss[256];
    __shared__ float sstat[2];
    int grp = blockIdx.x, b = blockIdx.y;
    int t = threadIdx.x;
    size_t base = ((size_t)b * CDIM + grp * 16) * HW;
    int n = 16 * HW;
    float s = 0.f, ss = 0.f;
    for (int e = t; e < n; e += 256) {
        float v = data[base + e];
        s += v; ss += v * v;
    }
    rs[t] = s; rss[t] = ss;
    __syncthreads();
    for (int o = 128; o > 0; o >>= 1) {
        if (t < o) { rs[t] += rs[t + o]; rss[t] += rss[t + o]; }
        __syncthreads();
    }
    if (t == 0) {
        float mean = rs[0] / (float)n;
        float var  = rss[0] / (float)n - mean * mean;
        sstat[0] = mean;
        sstat[1] = rsqrtf(var + 1e-5f);
    }
    __syncthreads();
    float mean = sstat[0], rstd = sstat[1];
    float* out = dst ? dst : data;
    for (int e = t; e < n; e += 256) {
        int c = grp * 16 + e / HW;
        float v = (data[base + e] - mean) * rstd * w[c] + bgn[c];
        if (addsrc) v += addsrc[base + e];
        out[base + e] = v;
    }
}

// ---------------- depthwise 3x3 s2 conv + bias + stride-2 pool add ----------------
__global__ __launch_bounds__(256)
void dwpool_kernel(const float* __restrict__ x, const float* __restrict__ w,
                   const float* __restrict__ bias, float* __restrict__ tq)
{
    int idx = blockIdx.x * 256 + threadIdx.x;
    if (idx >= NB * CIN * PQ) return;
    int p = idx % PQ;
    int c = (idx / PQ) % CIN;
    int b = idx / (PQ * CIN);
    int py = p / 28, px = p - py * 28;
    const float* xb = x + ((size_t)b * CIN + c) * NNF;
    float acc = bias[c] + xb[(2 * py) * HIN + 2 * px];   // pool term
#pragma unroll
    for (int ky = 0; ky < 3; ky++) {
        int iy = 2 * py - 1 + ky;
        if ((unsigned)iy >= (unsigned)HIN) continue;
#pragma unroll
        for (int kx = 0; kx < 3; kx++) {
            int ix = 2 * px - 1 + kx;
            if ((unsigned)ix >= (unsigned)HIN) continue;
            acc += w[c * 9 + ky * 3 + kx] * xb[iy * HIN + ix];
        }
    }
    tq[idx] = acc;
}

// ---------------- head-axis l2 norm for K (in place) ----------------
__global__ __launch_bounds__(256)
void hn_k_kernel(float* __restrict__ k)
{
    int idx = blockIdx.x * 256 + threadIdx.x;
    if (idx >= NB * HD * NNF) return;
    int nidx = idx % NNF;
    int d = (idx / NNF) % HD;
    int b = idx / (NNF * HD);
    float v[NHEADS];
    float s = 0.f;
#pragma unroll
    for (int h = 0; h < NHEADS; h++) {
        v[h] = k[((size_t)b * CDIM + h * HD + d) * NNF + nidx];
        s += v[h] * v[h];
    }
    float inv = 1.f / fmaxf(sqrtf(s), 1e-12f);
#pragma unroll
    for (int h = 0; h < NHEADS; h++)
        k[((size_t)b * CDIM + h * HD + d) * NNF + nidx] = v[h] * inv;
}

// ---------------- head-axis l2 norm for Q + transpose to [b][p][c] ----------------
__global__ __launch_bounds__(256)
void hn_q_kernel(const float* __restrict__ q, float* __restrict__ qn)
{
    int idx = blockIdx.x * 256 + threadIdx.x;
    if (idx >= NB * HD * PQ) return;
    int p = idx % PQ;
    int d = (idx / PQ) % HD;
    int b = idx / (PQ * HD);
    float v[NHEADS];
    float s = 0.f;
#pragma unroll
    for (int h = 0; h < NHEADS; h++) {
        v[h] = q[((size_t)b * CDIM + h * HD + d) * PQ + p];
        s += v[h] * v[h];
    }
    float inv = 1.f / fmaxf(sqrtf(s), 1e-12f);
#pragma unroll
    for (int h = 0; h < NHEADS; h++)
        qn[((size_t)b * PQ + p) * CDIM + h * HD + d] = v[h] * inv;
}

// ---------------- fused QK^T * scale + bias gather + th1 head-mix ----------------
// s1[b][o][q][n] = sum_i th1[o][i] * (scale * qn_i . kn_i + biases[i, idx[q,n]])
// grid: (49 n-tiles of 64, 49 q-tiles of 16, 4)
__global__ __launch_bounds__(256)
void attn_s1_kernel(const float* __restrict__ qn, const float* __restrict__ kn,
                    const float* __restrict__ th1, const float* __restrict__ ab,
                    const int* __restrict__ bidx, float* __restrict__ s1)
{
    extern __shared__ __align__(16) float sm[];
    float* qns  = sm;                  // 16*512
    float* kns  = sm + 16 * 512;       // 64*68
    float* th1s = sm + 16 * 512 + 64 * 68; // 64
    int b  = blockIdx.z;
    int q0 = blockIdx.y * 16;
    int n0 = blockIdx.x * 64;
    int t  = threadIdx.x;
    int qq = t >> 4, lane = t & 15, nb = lane * 4;

    if (t < 64) th1s[t] = th1[t];
#pragma unroll
    for (int it = 0; it < 32; it++) {
        int idx = t + it * 256;
        qns[idx] = qn[((size_t)b * PQ + q0 + (idx >> 9)) * CDIM + (idx & 511)];
    }
    int4 bi = *(const int4*)&bidx[(size_t)(q0 + qq) * NNF + n0 + nb];

    float acc[NHEADS][4];
#pragma unroll
    for (int o = 0; o < NHEADS; o++)
#pragma unroll
        for (int j = 0; j < 4; j++) acc[o][j] = 0.f;

    for (int i = 0; i < NHEADS; i++) {
        __syncthreads();
#pragma unroll
        for (int it = 0; it < 16; it++) {
            int idx = t + it * 256;
            int d = idx >> 6, nn = idx & 63;
            kns[d * 68 + nn] = kn[((size_t)b * CDIM + i * HD + d) * NNF + n0 + nn];
        }
        __syncthreads();
        float s0 = 0.f, s1v = 0.f, s2 = 0.f, s3 = 0.f;
        const float* qrow = &qns[qq * CDIM + i * HD];
#pragma unroll 16
        for (int d = 0; d < HD; d++) {
            float qv = qrow[d];
            float4 kv = *(const float4*)&kns[d * 68 + nb];
            s0 += qv * kv.x; s1v += qv * kv.y; s2 += qv * kv.z; s3 += qv * kv.w;
        }
        const float* abr = ab + i * NNF;
        float t0 = s0  * SCALE + abr[bi.x];
        float t1 = s1v * SCALE + abr[bi.y];
        float t2 = s2  * SCALE + abr[bi.z];
        float t3 = s3  * SCALE + abr[bi.w];
#pragma unroll
        for (int o = 0; o < NHEADS; o++) {
            float wv = th1s[o * 8 + i];
            acc[o][0] += wv * t0; acc[o][1] += wv * t1;
            acc[o][2] += wv * t2; acc[o][3] += wv * t3;
        }
    }
#pragma unroll
    for (int o = 0; o < NHEADS; o++) {
        float4 v = make_float4(acc[o][0], acc[o][1], acc[o][2], acc[o][3]);
        *(float4*)&s1[(((size_t)b * NHEADS + o) * PQ + q0 + qq) * NNF + n0 + nb] = v;
    }
}

// ---------------- softmax over n + th2 head-mix ----------------
// one block per (q,b); 8 rows of 3136 in smem
__global__ __launch_bounds__(256)
void softmax_mix_kernel(const float* __restrict__ s1, const float* __restrict__ th2,
                        float* __restrict__ a2)
{
    extern __shared__ __align__(16) float rows[];   // 8*3136
    __shared__ float red[256];
    __shared__ float linv[NHEADS];
    __shared__ float th2s[64];
    int q = blockIdx.x, b = blockIdx.y, t = threadIdx.x;
    if (t < 64) th2s[t] = th2[t];
    size_t rowbase = ((size_t)b * NHEADS * PQ + q) * NNF;
    for (int o = 0; o < NHEADS; o++) {
        const float* src = s1 + rowbase + (size_t)o * PQ * NNF;
        float* r = rows + o * NNF;
        float mx = -1e30f;
        for (int n = t; n < NNF; n += 256) { float v = src[n]; r[n] = v; mx = fmaxf(mx, v); }
        red[t] = mx; __syncthreads();
        for (int s = 128; s > 0; s >>= 1) { if (t < s) red[t] = fmaxf(red[t], red[t + s]); __syncthreads(); }
        mx = red[0]; __syncthreads();
        float sum = 0.f;
        for (int n = t; n < NNF; n += 256) { float e = __expf(r[n] - mx); r[n] = e; sum += e; }
        red[t] = sum; __syncthreads();
        for (int s = 128; s > 0; s >>= 1) { if (t < s) red[t] += red[t + s]; __syncthreads(); }
        if (t == 0) linv[o] = 1.f / red[0];
        __syncthreads();
    }
    float li[NHEADS];
#pragma unroll
    for (int i = 0; i < NHEADS; i++) li[i] = linv[i];
    for (int n = t; n < NNF; n += 256) {
        float p[NHEADS];
#pragma unroll
        for (int i = 0; i < NHEADS; i++) p[i] = rows[i * NNF + n] * li[i];
#pragma unroll
        for (int o = 0; o < NHEADS; o++) {
            float s = 0.f;
#pragma unroll
            for (int i = 0; i < NHEADS; i++) s += th2s[o * 8 + i] * p[i];
            a2[rowbase + (size_t)o * PQ * NNF + n] = s;
        }
    }
}

// ---------------- AV GEMM + v_local add ----------------
// out[b][o*64+d][q] = sum_n a2[b][o][q][n] * v[b][o*64+d][n]  + vloc[b][o*64+d][q]
__global__ __launch_bounds__(256)
void av_kernel(const float* __restrict__ a2, const float* __restrict__ v,
               const float* __restrict__ vloc, float* __restrict__ out)
{
    __shared__ __align__(16) float As[64 * 17];
    __shared__ __align__(16) float Xs[16 * 68];
    int b = blockIdx.z, o = blockIdx.y, q0 = blockIdx.x * 64;
    int t = threadIdx.x, ty = t >> 4, tx = t & 15;
    const float* vb = v  + ((size_t)b * CDIM + o * HD) * NNF;
    const float* ab = a2 + (((size_t)b * NHEADS + o) * PQ) * NNF;

    float acc[4][4];
#pragma unroll
    for (int i = 0; i < 4; i++)
#pragma unroll
        for (int j = 0; j < 4; j++) acc[i][j] = 0.f;

    for (int n0 = 0; n0 < NNF; n0 += 16) {
#pragma unroll
        for (int it = 0; it < 4; it++) {
            int idx = t + it * 256;
            int dd = idx >> 4, kk = idx & 15;
            As[dd * 17 + kk] = vb[(size_t)dd * NNF + n0 + kk];
        }
#pragma unroll
        for (int it = 0; it < 4; it++) {
            int idx = t + it * 256;
            int qq = idx >> 4, kk = idx & 15;
            int p = q0 + qq;
            Xs[kk * 68 + qq] = (p < PQ) ? ab[(size_t)p * NNF + n0 + kk] : 0.f;
        }
        __syncthreads();
#pragma unroll
        for (int kk = 0; kk < 16; kk++) {
            float a0 = As[(ty * 4 + 0) * 17 + kk];
            float a1 = As[(ty * 4 + 1) * 17 + kk];
            float a2v = As[(ty * 4 + 2) * 17 + kk];
            float a3 = As[(ty * 4 + 3) * 17 + kk];
            float4 xv = *(const float4*)&Xs[kk * 68 + tx * 4];
            acc[0][0] += a0 * xv.x; acc[0][1] += a0 * xv.y; acc[0][2] += a0 * xv.z; acc[0][3] += a0 * xv.w;
            acc[1][0] += a1 * xv.x; acc[1][1] += a1 * xv.y; acc[1][2] += a1 * xv.z; acc[1][3] += a1 * xv.w;
            acc[2][0] += a2v * xv.x; acc[2][1] += a2v * xv.y; acc[2][2] += a2v * xv.z; acc[2][3] += a2v * xv.w;
            acc[3][0] += a3 * xv.x; acc[3][1] += a3 * xv.y; acc[3][2] += a3 * xv.z; acc[3][3] += a3 * xv.w;
        }
        __syncthreads();
    }
#pragma unroll
    for (int i = 0; i < 4; i++) {
        int c = o * HD + ty * 4 + i;
        const float* vl = vloc + ((size_t)b * CDIM + c) * PQ;
        float* ob = out + ((size_t)b * CDIM + c) * PQ;
#pragma unroll
        for (int j = 0; j < 4; j++) {
            int p = q0 + tx * 4 + j;
            if (p < PQ) ob[p] = acc[i][j] + vl[p];
        }
    }
}

// ---------------- launch ----------------
extern "C" void kernel_launch(void* const* d_in, const int* in_sizes, int n_in,
                              void* d_out, int out_size)
{
    const float* x         = (const float*)d_in[0];
    const float* q_local_w = (const float*)d_in[1];
    const float* q_local_b = (const float*)d_in[2];
    const float* q_proj_w  = (const float*)d_in[3];
    const float* q_proj_b  = (const float*)d_in[4];
    const float* q_gn_w    = (const float*)d_in[5];
    const float* q_gn_b    = (const float*)d_in[6];
    const float* k_w       = (const float*)d_in[7];
    const float* k_gn_w    = (const float*)d_in[8];
    const float* k_gn_b    = (const float*)d_in[9];
    const float* v_w       = (const float*)d_in[10];
    const float* v_gn_w    = (const float*)d_in[11];
    const float* v_gn_b    = (const float*)d_in[12];
    const float* loc_w     = (const float*)d_in[13];
    const float* loc_b     = (const float*)d_in[14];
    const float* loc_gn_w  = (const float*)d_in[15];
    const float* loc_gn_b  = (const float*)d_in[16];
    const float* th1_w     = (const float*)d_in[17];
    const float* th2_w     = (const float*)d_in[18];
    const float* out_w     = (const float*)d_in[19];
    const float* out_gn_w  = (const float*)d_in[20];
    const float* out_gn_b  = (const float*)d_in[21];
    const float* proj_w    = (const float*)d_in[22];
    const float* proj_b    = (const float*)d_in[23];
    const float* proj_gn_w = (const float*)d_in[24];
    const float* proj_gn_b = (const float*)d_in[25];
    const float* attn_bias = (const float*)d_in[26];
    const int*   bias_idxs = (const int*)d_in[27];
    float* out = (float*)d_out;

    float* S = nullptr;
    cudaGetSymbolAddress((void**)&S, g_scratch);
    float* xproj = S + OFF_XPROJ;
    float* tq    = S + OFF_TQ;
    float* qbuf  = S + OFF_Q;
    float* qn    = S + OFF_QN;
    float* kbuf  = S + OFF_K;
    float* vbuf  = S + OFF_V;
    float* vloc  = S + OFF_VLOC;
    float* o1    = S + OFF_O1;
    float* o2    = S + OFF_O2;
    float* s1    = S + OFF_S1;
    float* a2    = S + OFF_A2;

    cudaFuncSetAttribute(attn_s1_kernel, cudaFuncAttributeMaxDynamicSharedMemorySize, 50432);
    cudaFuncSetAttribute(softmax_mix_kernel, cudaFuncAttributeMaxDynamicSharedMemorySize, 100352);

    dim3 blk(256);

    // proj path: conv3x3 s2 (256->512) + bias, then GN in place
    conv3x3_kernel<<<dim3(13, 8, NB), blk>>>(x, proj_w, proj_b, xproj, 256, 256, 512, 512);
    gn_kernel<<<dim3(32, NB), blk>>>(xproj, proj_gn_w, proj_gn_b, PQ, nullptr, nullptr);

    // q path
    dwpool_kernel<<<dim3((NB * CIN * PQ + 255) / 256), blk>>>(x, q_local_w, q_local_b, tq);
    gemm1x1_kernel<<<dim3(13, 8, NB), blk>>>(q_proj_w, tq, q_proj_b, qbuf, 512, 256, PQ, 0);
    gn_kernel<<<dim3(32, NB), blk>>>(qbuf, q_gn_w, q_gn_b, PQ, nullptr, nullptr);

    // k path
    gemm1x1_kernel<<<dim3(49, 8, NB), blk>>>(k_w, x, nullptr, kbuf, 512, 256, NNF, 0);
    gn_kernel<<<dim3(32, NB), blk>>>(kbuf, k_gn_w, k_gn_b, NNF, nullptr, nullptr);
    hn_k_kernel<<<dim3((NB * HD * NNF + 255) / 256), blk>>>(kbuf);

    // v path
    gemm1x1_kernel<<<dim3(49, 8, NB), blk>>>(v_w, x, nullptr, vbuf, 512, 256, NNF, 0);
    gn_kernel<<<dim3(32, NB), blk>>>(vbuf, v_gn_w, v_gn_b, NNF, nullptr, nullptr);

    // v_local: grouped conv3x3 s2 (8 groups of 64) + bias, GN in place
    conv3x3_kernel<<<dim3(13, 8, NB), blk>>>(vbuf, loc_w, loc_b, vloc, 64, 512, 64, 512);
    gn_kernel<<<dim3(32, NB), blk>>>(vloc, loc_gn_w, loc_gn_b, PQ, nullptr, nullptr);

    // q l2norm over heads + transpose
    hn_q_kernel<<<dim3((NB * HD * PQ + 255) / 256), blk>>>(qbuf, qn);

    // attention scores + bias + th1
    attn_s1_kernel<<<dim3(49, 49, NB), blk, 50432>>>(qn, kbuf, th1_w, attn_bias, bias_idxs, s1);

    // softmax + th2
    softmax_mix_kernel<<<dim3(PQ, NB), blk, 100352>>>(s1, th2_w, a2);

    // AV + v_local
    av_kernel<<<dim3(13, 8, NB), blk>>>(a2, vbuf, vloc, o1);

    // hardswish -> out 1x1 conv (512->512)
    gemm1x1_kernel<<<dim3(13, 8, NB), blk>>>(out_w, o1, nullptr, o2, 512, 512, PQ, 1);

    // final GN + residual add -> d_out
    gn_kernel<<<dim3(32, NB), blk>>>(o2, out_gn_w, out_gn_b, PQ, xproj, out);
}

// round 4
// speedup vs baseline: 1.0345x; 1.0345x over previous
#include <cuda_runtime.h>
#include <cstddef>

#define NB     4
#define CIN    256
#define CDIM   512
#define HIN    56
#define NNF    3136      // 56*56
#define PQ     784       // 28*28
#define NHEADS 8
#define HD     64
#define SCALE  0.125f
#define NTILES 49        // 3136/64

// ---------------- scratch layout (single __device__ array) ----------------
#define SZ_MAP  1605632ull     // 4*512*784
#define SZ_TQ   802816ull      // 4*256*784
#define SZ_KV   6422528ull     // 4*512*3136
#define SZ_ATT  78675968ull    // 4*8*784*3136
#define SZ_PS   1229312ull     // 4*784*8*49
#define SZ_LI   25088ull       // 4*784*8

#define OFF_XPROJ 0ull
#define OFF_TQ    (OFF_XPROJ + SZ_MAP)
#define OFF_Q     (OFF_TQ    + SZ_TQ)
#define OFF_QN    (OFF_Q     + SZ_MAP)
#define OFF_K     (OFF_QN    + SZ_MAP)
#define OFF_V     (OFF_K     + SZ_KV)
#define OFF_VLOC  (OFF_V     + SZ_KV)
#define OFF_O1    (OFF_VLOC  + SZ_MAP)
#define OFF_O2    (OFF_O1    + SZ_MAP)
#define OFF_S1    (OFF_O2    + SZ_MAP)
#define OFF_A2    (OFF_S1    + SZ_ATT)
#define OFF_PS    (OFF_A2    + SZ_ATT)
#define OFF_LI    (OFF_PS    + SZ_PS)
#define SCRATCH_TOTAL (OFF_LI + SZ_LI)

__device__ float g_scratch[SCRATCH_TOTAL];

// ---------------- packed f32x2 helpers ----------------
__device__ __forceinline__ void ffma2(float2& acc, const float2 a, const float2 b) {
    asm("fma.rn.f32x2 %0, %1, %2, %0;"
        : "+l"(reinterpret_cast<unsigned long long&>(acc))
        : "l"(reinterpret_cast<const unsigned long long&>(a)),
          "l"(reinterpret_cast<const unsigned long long&>(b)));
}
__device__ __forceinline__ float2 dup2(float v) {
    float2 r;
    asm("mov.b64 %0, {%1, %1};"
        : "=l"(reinterpret_cast<unsigned long long&>(r)) : "f"(v));
    return r;
}

// ---------------- generic tiled GEMM for 1x1 convs (f32x2) ----------------
// Y[b][m][p] = sum_k A[m][k] * X[b][k][p]  (+bias[m]), optional hardswish on X
__global__ __launch_bounds__(256)
void gemm1x1_kernel(const float* __restrict__ A, const float* __restrict__ X,
                    const float* __restrict__ bias, float* __restrict__ Y,
                    int M, int K, int P, int hsw)
{
    __shared__ __align__(16) float2 As2[64 * 17];
    __shared__ __align__(16) float  Xs[16 * 68];
    int b  = blockIdx.z;
    int m0 = blockIdx.y * 64;
    int p0 = blockIdx.x * 64;
    int t  = threadIdx.x;
    int ty = t >> 4, tx = t & 15;

    float2 acc[4][2];
#pragma unroll
    for (int i = 0; i < 4; i++) { acc[i][0] = make_float2(0.f, 0.f); acc[i][1] = make_float2(0.f, 0.f); }

    for (int k0 = 0; k0 < K; k0 += 16) {
#pragma unroll
        for (int it = 0; it < 4; it++) {
            int idx = t + it * 256;
            int m = idx >> 4, k = idx & 15;
            float v = A[(size_t)(m0 + m) * K + k0 + k];
            As2[m * 17 + k] = make_float2(v, v);
        }
#pragma unroll
        for (int it = 0; it < 4; it++) {
            int idx = t + it * 256;
            int kk = idx >> 6, pp = idx & 63;
            int p = p0 + pp;
            float v = 0.f;
            if (p < P) v = X[((size_t)b * K + k0 + kk) * P + p];
            if (hsw) {
                float c = fminf(fmaxf(v + 3.f, 0.f), 6.f);
                v = v * c * (1.f / 6.f);
            }
            Xs[kk * 68 + pp] = v;
        }
        __syncthreads();
#pragma unroll
        for (int kk = 0; kk < 16; kk++) {
            float2 a0 = As2[(ty * 4 + 0) * 17 + kk];
            float2 a1 = As2[(ty * 4 + 1) * 17 + kk];
            float2 a2 = As2[(ty * 4 + 2) * 17 + kk];
            float2 a3 = As2[(ty * 4 + 3) * 17 + kk];
            float2 x01 = *(const float2*)&Xs[kk * 68 + tx * 4];
            float2 x23 = *(const float2*)&Xs[kk * 68 + tx * 4 + 2];
            ffma2(acc[0][0], a0, x01); ffma2(acc[0][1], a0, x23);
            ffma2(acc[1][0], a1, x01); ffma2(acc[1][1], a1, x23);
            ffma2(acc[2][0], a2, x01); ffma2(acc[2][1], a2, x23);
            ffma2(acc[3][0], a3, x01); ffma2(acc[3][1], a3, x23);
        }
        __syncthreads();
    }
#pragma unroll
    for (int i = 0; i < 4; i++) {
        int m = m0 + ty * 4 + i;
        float bv = bias ? bias[m] : 0.f;
        float* yb = Y + ((size_t)b * M + m) * P;
        float v4[4] = { acc[i][0].x + bv, acc[i][0].y + bv, acc[i][1].x + bv, acc[i][1].y + bv };
#pragma unroll
        for (int j = 0; j < 4; j++) {
            int p = p0 + tx * 4 + j;
            if (p < P) yb[p] = v4[j];
        }
    }
}

// ---------------- implicit-GEMM 3x3 stride-2 pad-1 conv (grouped, f32x2) ----------------
__global__ __launch_bounds__(256)
void conv3x3_kernel(const float* __restrict__ X, const float* __restrict__ W,
                    const float* __restrict__ bias, float* __restrict__ Y,
                    int CinPG, int CinTot, int CoutPG, int Cout)
{
    __shared__ __align__(16) float2 As2[64 * 17];
    __shared__ __align__(16) float  Xs[16 * 68];
    int b  = blockIdx.z;
    int m0 = blockIdx.y * 64;
    int p0 = blockIdx.x * 64;
    int g  = m0 / CoutPG;
    int K  = CinPG * 9;
    int t  = threadIdx.x;
    int ty = t >> 4, tx = t & 15;

    const float* Xb = X + (size_t)(b * CinTot + g * CinPG) * NNF;

    float2 acc[4][2];
#pragma unroll
    for (int i = 0; i < 4; i++) { acc[i][0] = make_float2(0.f, 0.f); acc[i][1] = make_float2(0.f, 0.f); }

    for (int k0 = 0; k0 < K; k0 += 16) {
#pragma unroll
        for (int it = 0; it < 4; it++) {
            int idx = t + it * 256;
            int m = idx >> 4, k = idx & 15;
            float v = W[(size_t)(m0 + m) * K + k0 + k];
            As2[m * 17 + k] = make_float2(v, v);
        }
#pragma unroll
        for (int it = 0; it < 4; it++) {
            int idx = t + it * 256;
            int kk = idx >> 6, pp = idx & 63;
            int k = k0 + kk;
            int ci = k / 9, r9 = k - ci * 9;
            int ky = r9 / 3, kx = r9 - ky * 3;
            int p = p0 + pp;
            float v = 0.f;
            if (p < PQ) {
                int py = p / 28, px = p - py * 28;
                int iy = 2 * py - 1 + ky, ix = 2 * px - 1 + kx;
                if ((unsigned)iy < (unsigned)HIN && (unsigned)ix < (unsigned)HIN)
                    v = Xb[(size_t)ci * NNF + iy * HIN + ix];
            }
            Xs[kk * 68 + pp] = v;
        }
        __syncthreads();
#pragma unroll
        for (int kk = 0; kk < 16; kk++) {
            float2 a0 = As2[(ty * 4 + 0) * 17 + kk];
            float2 a1 = As2[(ty * 4 + 1) * 17 + kk];
            float2 a2 = As2[(ty * 4 + 2) * 17 + kk];
            float2 a3 = As2[(ty * 4 + 3) * 17 + kk];
            float2 x01 = *(const float2*)&Xs[kk * 68 + tx * 4];
            float2 x23 = *(const float2*)&Xs[kk * 68 + tx * 4 + 2];
            ffma2(acc[0][0], a0, x01); ffma2(acc[0][1], a0, x23);
            ffma2(acc[1][0], a1, x01); ffma2(acc[1][1], a1, x23);
            ffma2(acc[2][0], a2, x01); ffma2(acc[2][1], a2, x23);
            ffma2(acc[3][0], a3, x01); ffma2(acc[3][1], a3, x23);
        }
        __syncthreads();
    }
#pragma unroll
    for (int i = 0; i < 4; i++) {
        int m = m0 + ty * 4 + i;
        float bv = bias ? bias[m] : 0.f;
        float* yb = Y + ((size_t)b * Cout + m) * PQ;
        float v4[4] = { acc[i][0].x + bv, acc[i][0].y + bv, acc[i][1].x + bv, acc[i][1].y + bv };
#pragma unroll
        for (int j = 0; j < 4; j++) {
            int p = p0 + tx * 4 + j;
            if (p < PQ) yb[p] = v4[j];
        }
    }
}

// ---------------- GroupNorm (in-place or to dst, optional residual add) ----------------
__global__ __launch_bounds__(256)
void gn_kernel(float* __restrict__ data, const float* __restrict__ w,
               const float* __restrict__ bgn, int HW,
               const float* __restrict__ addsrc, float* __restrict__ dst)
{
    __shared__ float rs[256], rss[256];
    __shared__ float sstat[2];
    int grp = blockIdx.x, b = blockIdx.y;
    int t = threadIdx.x;
    size_t base = ((size_t)b * CDIM + grp * 16) * HW;
    int n = 16 * HW;
    float s = 0.f, ss = 0.f;
    for (int e = t; e < n; e += 256) {
        float v = data[base + e];
        s += v; ss += v * v;
    }
    rs[t] = s; rss[t] = ss;
    __syncthreads();
    for (int o = 128; o > 0; o >>= 1) {
        if (t < o) { rs[t] += rs[t + o]; rss[t] += rss[t + o]; }
        __syncthreads();
    }
    if (t == 0) {
        float mean = rs[0] / (float)n;
        float var  = rss[0] / (float)n - mean * mean;
        sstat[0] = mean;
        sstat[1] = rsqrtf(var + 1e-5f);
    }
    __syncthreads();
    float mean = sstat[0], rstd = sstat[1];
    float* out = dst ? dst : data;
    for (int e = t; e < n; e += 256) {
        int c = grp * 16 + e / HW;
        float v = (data[base + e] - mean) * rstd * w[c] + bgn[c];
        if (addsrc) v += addsrc[base + e];
        out[base + e] = v;
    }
}

// ---------------- depthwise 3x3 s2 conv + bias + stride-2 pool add ----------------
__global__ __launch_bounds__(256)
void dwpool_kernel(const float* __restrict__ x, const float* __restrict__ w,
                   const float* __restrict__ bias, float* __restrict__ tq)
{
    int idx = blockIdx.x * 256 + threadIdx.x;
    if (idx >= NB * CIN * PQ) return;
    int p = idx % PQ;
    int c = (idx / PQ) % CIN;
    int b = idx / (PQ * CIN);
    int py = p / 28, px = p - py * 28;
    const float* xb = x + ((size_t)b * CIN + c) * NNF;
    float acc = bias[c] + xb[(2 * py) * HIN + 2 * px];   // pool term
#pragma unroll
    for (int ky = 0; ky < 3; ky++) {
        int iy = 2 * py - 1 + ky;
        if ((unsigned)iy >= (unsigned)HIN) continue;
#pragma unroll
        for (int kx = 0; kx < 3; kx++) {
            int ix = 2 * px - 1 + kx;
            if ((unsigned)ix >= (unsigned)HIN) continue;
            acc += w[c * 9 + ky * 3 + kx] * xb[iy * HIN + ix];
        }
    }
    tq[idx] = acc;
}

// ---------------- head-axis l2 norm for K (in place) ----------------
__global__ __launch_bounds__(256)
void hn_k_kernel(float* __restrict__ k)
{
    int idx = blockIdx.x * 256 + threadIdx.x;
    if (idx >= NB * HD * NNF) return;
    int nidx = idx % NNF;
    int d = (idx / NNF) % HD;
    int b = idx / (NNF * HD);
    float v[NHEADS];
    float s = 0.f;
#pragma unroll
    for (int h = 0; h < NHEADS; h++) {
        v[h] = k[((size_t)b * CDIM + h * HD + d) * NNF + nidx];
        s += v[h] * v[h];
    }
    float inv = 1.f / fmaxf(sqrtf(s), 1e-12f);
#pragma unroll
    for (int h = 0; h < NHEADS; h++)
        k[((size_t)b * CDIM + h * HD + d) * NNF + nidx] = v[h] * inv;
}

// ---------------- head-axis l2 norm for Q + transpose to [b][p][c] ----------------
__global__ __launch_bounds__(256)
void hn_q_kernel(const float* __restrict__ q, float* __restrict__ qn)
{
    int idx = blockIdx.x * 256 + threadIdx.x;
    if (idx >= NB * HD * PQ) return;
    int p = idx % PQ;
    int d = (idx / PQ) % HD;
    int b = idx / (PQ * HD);
    float v[NHEADS];
    float s = 0.f;
#pragma unroll
    for (int h = 0; h < NHEADS; h++) {
        v[h] = q[((size_t)b * CDIM + h * HD + d) * PQ + p];
        s += v[h] * v[h];
    }
    float inv = 1.f / fmaxf(sqrtf(s), 1e-12f);
#pragma unroll
    for (int h = 0; h < NHEADS; h++)
        qn[((size_t)b * PQ + p) * CDIM + h * HD + d] = v[h] * inv;
}

// ---------------- fused QK^T*scale + bias + th1 mix + exp + partial row sums ----------------
// e[b][o][q][n] = exp( sum_i th1[o][i]*(scale*qn_i.kn_i + bias[i,idx[q,n]]) )
// partial[( (b*PQ+q)*8+o )*49 + ntile] = sum over this 64-n tile
__global__ __launch_bounds__(256)
void attn_s1_kernel(const float* __restrict__ qn, const float* __restrict__ kn,
                    const float* __restrict__ th1, const float* __restrict__ ab,
                    const int* __restrict__ bidx, float* __restrict__ s1,
                    float* __restrict__ partial)
{
    extern __shared__ __align__(16) float sm[];
    float*  qns  = sm;                          // 16*512
    float*  kns  = sm + 16 * 512;               // 64*68
    float2* th1s = (float2*)(sm + 16 * 512 + 64 * 68); // 64 float2 (dup'd)
    int b  = blockIdx.z;
    int q0 = blockIdx.y * 16;
    int n0 = blockIdx.x * 64;
    int t  = threadIdx.x;
    int qq = t >> 4, tx = t & 15, nb = tx * 4;

    if (t < 64) { float w = th1[t]; th1s[t] = make_float2(w, w); }
#pragma unroll
    for (int it = 0; it < 32; it++) {
        int idx = t + it * 256;
        qns[idx] = qn[((size_t)b * PQ + q0 + (idx >> 9)) * CDIM + (idx & 511)];
    }
    int4 bi = *(const int4*)&bidx[(size_t)(q0 + qq) * NNF + n0 + nb];

    float2 acc[NHEADS][2];
#pragma unroll
    for (int o = 0; o < NHEADS; o++) { acc[o][0] = make_float2(0.f, 0.f); acc[o][1] = make_float2(0.f, 0.f); }

    for (int i = 0; i < NHEADS; i++) {
        __syncthreads();
#pragma unroll
        for (int it = 0; it < 16; it++) {
            int idx = t + it * 256;
            int d = idx >> 6, nn = idx & 63;
            kns[d * 68 + nn] = kn[((size_t)b * CDIM + i * HD + d) * NNF + n0 + nn];
        }
        __syncthreads();
        float2 s01 = make_float2(0.f, 0.f), s23 = make_float2(0.f, 0.f);
        const float* qrow = &qns[qq * CDIM + i * HD];
#pragma unroll 16
        for (int d = 0; d < HD; d++) {
            float2 qp = dup2(qrow[d]);
            float2 k01 = *(const float2*)&kns[d * 68 + nb];
            float2 k23 = *(const float2*)&kns[d * 68 + nb + 2];
            ffma2(s01, qp, k01);
            ffma2(s23, qp, k23);
        }
        const float* abr = ab + i * NNF;
        float2 t01 = make_float2(s01.x * SCALE + abr[bi.x], s01.y * SCALE + abr[bi.y]);
        float2 t23 = make_float2(s23.x * SCALE + abr[bi.z], s23.y * SCALE + abr[bi.w]);
#pragma unroll
        for (int o = 0; o < NHEADS; o++) {
            float2 wv = th1s[o * 8 + i];
            ffma2(acc[o][0], wv, t01);
            ffma2(acc[o][1], wv, t23);
        }
    }
#pragma unroll
    for (int o = 0; o < NHEADS; o++) {
        float4 ev;
        ev.x = __expf(acc[o][0].x);
        ev.y = __expf(acc[o][0].y);
        ev.z = __expf(acc[o][1].x);
        ev.w = __expf(acc[o][1].y);
        *(float4*)&s1[(((size_t)b * NHEADS + o) * PQ + q0 + qq) * NNF + n0 + nb] = ev;
        float ps = (ev.x + ev.y) + (ev.z + ev.w);
#pragma unroll
        for (int off = 8; off > 0; off >>= 1)
            ps += __shfl_xor_sync(0xffffffffu, ps, off);
        if (tx == 0)
            partial[(((size_t)b * PQ + q0 + qq) * NHEADS + o) * NTILES + blockIdx.x] = ps;
    }
}

// ---------------- reduce partial sums -> 1/l ----------------
__global__ __launch_bounds__(256)
void reduce_l_kernel(const float* __restrict__ partial, float* __restrict__ linv)
{
    int idx = blockIdx.x * 256 + threadIdx.x;
    if (idx >= NB * PQ * NHEADS) return;
    const float* p = partial + (size_t)idx * NTILES;
    float s = 0.f;
#pragma unroll
    for (int i = 0; i < NTILES; i++) s += p[i];
    linv[idx] = 1.f / s;
}

// ---------------- normalize + th2 head-mix (streaming) ----------------
// a2[b][o'][q][n] = sum_o th2[o'][o] * e[b][o][q][n] * linv[b][q][o]
__global__ __launch_bounds__(256)
void mix_kernel(const float* __restrict__ e, const float* __restrict__ linv,
                const float* __restrict__ th2, float* __restrict__ a2)
{
    __shared__ float th2s[64];
    int q = blockIdx.x, b = blockIdx.y, t = threadIdx.x;
    if (t < 64) th2s[t] = th2[t];
    __syncthreads();
    float li[NHEADS];
#pragma unroll
    for (int o = 0; o < NHEADS; o++)
        li[o] = linv[((size_t)b * PQ + q) * NHEADS + o];
    size_t base = ((size_t)b * NHEADS * PQ + q) * NNF;   // + o*PQ*NNF
    for (int n = t * 4; n < NNF; n += 1024) {
        float4 p[NHEADS];
#pragma unroll
        for (int i = 0; i < NHEADS; i++) {
            float4 v = *(const float4*)&e[base + (size_t)i * PQ * NNF + n];
            p[i] = make_float4(v.x * li[i], v.y * li[i], v.z * li[i], v.w * li[i]);
        }
#pragma unroll
        for (int o = 0; o < NHEADS; o++) {
            float4 s = make_float4(0.f, 0.f, 0.f, 0.f);
#pragma unroll
            for (int i = 0; i < NHEADS; i++) {
                float w = th2s[o * 8 + i];
                s.x += w * p[i].x; s.y += w * p[i].y;
                s.z += w * p[i].z; s.w += w * p[i].w;
            }
            *(float4*)&a2[base + (size_t)o * PQ * NNF + n] = s;
        }
    }
}

// ---------------- AV GEMM + v_local add (f32x2) ----------------
__global__ __launch_bounds__(256)
void av_kernel(const float* __restrict__ a2, const float* __restrict__ v,
               const float* __restrict__ vloc, float* __restrict__ out)
{
    __shared__ __align__(16) float2 As2[64 * 17];
    __shared__ __align__(16) float  Xs[16 * 68];
    int b = blockIdx.z, o = blockIdx.y, q0 = blockIdx.x * 64;
    int t = threadIdx.x, ty = t >> 4, tx = t & 15;
    const float* vb = v  + ((size_t)b * CDIM + o * HD) * NNF;
    const float* ab = a2 + (((size_t)b * NHEADS + o) * PQ) * NNF;

    float2 acc[4][2];
#pragma unroll
    for (int i = 0; i < 4; i++) { acc[i][0] = make_float2(0.f, 0.f); acc[i][1] = make_float2(0.f, 0.f); }

    for (int n0 = 0; n0 < NNF; n0 += 16) {
#pragma unroll
        for (int it = 0; it < 4; it++) {
            int idx = t + it * 256;
            int dd = idx >> 4, kk = idx & 15;
            float vv = vb[(size_t)dd * NNF + n0 + kk];
            As2[dd * 17 + kk] = make_float2(vv, vv);
        }
#pragma unroll
        for (int it = 0; it < 4; it++) {
            int idx = t + it * 256;
            int qq = idx >> 4, kk = idx & 15;
            int p = q0 + qq;
            Xs[kk * 68 + qq] = (p < PQ) ? ab[(size_t)p * NNF + n0 + kk] : 0.f;
        }
        __syncthreads();
#pragma unroll
        for (int kk = 0; kk < 16; kk++) {
            float2 a0 = As2[(ty * 4 + 0) * 17 + kk];
            float2 a1 = As2[(ty * 4 + 1) * 17 + kk];
            float2 a2v = As2[(ty * 4 + 2) * 17 + kk];
            float2 a3 = As2[(ty * 4 + 3) * 17 + kk];
            float2 x01 = *(const float2*)&Xs[kk * 68 + tx * 4];
            float2 x23 = *(const float2*)&Xs[kk * 68 + tx * 4 + 2];
            ffma2(acc[0][0], a0, x01);  ffma2(acc[0][1], a0, x23);
            ffma2(acc[1][0], a1, x01);  ffma2(acc[1][1], a1, x23);
            ffma2(acc[2][0], a2v, x01); ffma2(acc[2][1], a2v, x23);
            ffma2(acc[3][0], a3, x01);  ffma2(acc[3][1], a3, x23);
        }
        __syncthreads();
    }
#pragma unroll
    for (int i = 0; i < 4; i++) {
        int c = o * HD + ty * 4 + i;
        const float* vl = vloc + ((size_t)b * CDIM + c) * PQ;
        float* ob = out + ((size_t)b * CDIM + c) * PQ;
        float v4[4] = { acc[i][0].x, acc[i][0].y, acc[i][1].x, acc[i][1].y };
#pragma unroll
        for (int j = 0; j < 4; j++) {
            int p = q0 + tx * 4 + j;
            if (p < PQ) ob[p] = v4[j] + vl[p];
        }
    }
}

// ---------------- launch ----------------
extern "C" void kernel_launch(void* const* d_in, const int* in_sizes, int n_in,
                              void* d_out, int out_size)
{
    const float* x         = (const float*)d_in[0];
    const float* q_local_w = (const float*)d_in[1];
    const float* q_local_b = (const float*)d_in[2];
    const float* q_proj_w  = (const float*)d_in[3];
    const float* q_proj_b  = (const float*)d_in[4];
    const float* q_gn_w    = (const float*)d_in[5];
    const float* q_gn_b    = (const float*)d_in[6];
    const float* k_w       = (const float*)d_in[7];
    const float* k_gn_w    = (const float*)d_in[8];
    const float* k_gn_b    = (const float*)d_in[9];
    const float* v_w       = (const float*)d_in[10];
    const float* v_gn_w    = (const float*)d_in[11];
    const float* v_gn_b    = (const float*)d_in[12];
    const float* loc_w     = (const float*)d_in[13];
    const float* loc_b     = (const float*)d_in[14];
    const float* loc_gn_w  = (const float*)d_in[15];
    const float* loc_gn_b  = (const float*)d_in[16];
    const float* th1_w     = (const float*)d_in[17];
    const float* th2_w     = (const float*)d_in[18];
    const float* out_w     = (const float*)d_in[19];
    const float* out_gn_w  = (const float*)d_in[20];
    const float* out_gn_b  = (const float*)d_in[21];
    const float* proj_w    = (const float*)d_in[22];
    const float* proj_b    = (const float*)d_in[23];
    const float* proj_gn_w = (const float*)d_in[24];
    const float* proj_gn_b = (const float*)d_in[25];
    const float* attn_bias = (const float*)d_in[26];
    const int*   bias_idxs = (const int*)d_in[27];
    float* out = (float*)d_out;

    float* S = nullptr;
    cudaGetSymbolAddress((void**)&S, g_scratch);
    float* xproj = S + OFF_XPROJ;
    float* tq    = S + OFF_TQ;
    float* qbuf  = S + OFF_Q;
    float* qn    = S + OFF_QN;
    float* kbuf  = S + OFF_K;
    float* vbuf  = S + OFF_V;
    float* vloc  = S + OFF_VLOC;
    float* o1    = S + OFF_O1;
    float* o2    = S + OFF_O2;
    float* s1    = S + OFF_S1;
    float* a2    = S + OFF_A2;
    float* psum  = S + OFF_PS;
    float* linv  = S + OFF_LI;

    cudaFuncSetAttribute(attn_s1_kernel, cudaFuncAttributeMaxDynamicSharedMemorySize, 51200);

    dim3 blk(256);

    // proj path: conv3x3 s2 (256->512) + bias, then GN in place
    conv3x3_kernel<<<dim3(13, 8, NB), blk>>>(x, proj_w, proj_b, xproj, 256, 256, 512, 512);
    gn_kernel<<<dim3(32, NB), blk>>>(xproj, proj_gn_w, proj_gn_b, PQ, nullptr, nullptr);

    // q path
    dwpool_kernel<<<dim3((NB * CIN * PQ + 255) / 256), blk>>>(x, q_local_w, q_local_b, tq);
    gemm1x1_kernel<<<dim3(13, 8, NB), blk>>>(q_proj_w, tq, q_proj_b, qbuf, 512, 256, PQ, 0);
    gn_kernel<<<dim3(32, NB), blk>>>(qbuf, q_gn_w, q_gn_b, PQ, nullptr, nullptr);

    // k path
    gemm1x1_kernel<<<dim3(49, 8, NB), blk>>>(k_w, x, nullptr, kbuf, 512, 256, NNF, 0);
    gn_kernel<<<dim3(32, NB), blk>>>(kbuf, k_gn_w, k_gn_b, NNF, nullptr, nullptr);
    hn_k_kernel<<<dim3((NB * HD * NNF + 255) / 256), blk>>>(kbuf);

    // v path
    gemm1x1_kernel<<<dim3(49, 8, NB), blk>>>(v_w, x, nullptr, vbuf, 512, 256, NNF, 0);
    gn_kernel<<<dim3(32, NB), blk>>>(vbuf, v_gn_w, v_gn_b, NNF, nullptr, nullptr);

    // v_local: grouped conv3x3 s2 (8 groups of 64) + bias, GN in place
    conv3x3_kernel<<<dim3(13, 8, NB), blk>>>(vbuf, loc_w, loc_b, vloc, 64, 512, 64, 512);
    gn_kernel<<<dim3(32, NB), blk>>>(vloc, loc_gn_w, loc_gn_b, PQ, nullptr, nullptr);

    // q l2norm over heads + transpose
    hn_q_kernel<<<dim3((NB * HD * PQ + 255) / 256), blk>>>(qbuf, qn);

    // attention: exp(QK*scale + bias mixed by th1), partial row sums
    attn_s1_kernel<<<dim3(NTILES, 49, NB), blk, 51200>>>(qn, kbuf, th1_w, attn_bias,
                                                         bias_idxs, s1, psum);

    // row sums -> 1/l
    reduce_l_kernel<<<dim3((NB * PQ * NHEADS + 255) / 256), blk>>>(psum, linv);

    // normalize + th2 mix
    mix_kernel<<<dim3(PQ, NB), blk>>>(s1, linv, th2_w, a2);

    // AV + v_local
    av_kernel<<<dim3(13, NHEADS, NB), blk>>>(a2, vbuf, vloc, o1);

    // hardswish -> out 1x1 conv (512->512)
    gemm1x1_kernel<<<dim3(13, 8, NB), blk>>>(out_w, o1, nullptr, o2, 512, 512, PQ, 1);

    // final GN + residual add -> d_out
    gn_kernel<<<dim3(32, NB), blk>>>(o2, out_gn_w, out_gn_b, PQ, xproj, out);
}